// round 8
// baseline (speedup 1.0000x reference)
#include <cuda_runtime.h>
#include <cstdint>

// MultiBackScatter: three chained scatter-adds with UNIQUE (permutation) indices.
// Composition: out[idx0[idx1[idx2[i]]]] = x[i]; all other rows zero.
//
// R8 structure (best-known decomposition):
//   K1: pure-write zero sweep at the HBM write wall (6.9TB/s, unchanged from R7);
//       first 98 blocks also resolve the 3-level index chase into g_tgt
//       (latency hidden under their own zero-store stream).
//   K2: scatter with MLP=4 — each thread owns 4 chunks from DIFFERENT rows;
//       4 tgt loads, 4 x loads, 4 stores batched as independent groups so the
//       LSU has 4+ outstanding loads per thread (R7's MLP=1 was the bottleneck).
// g_tgt is a __device__ global; K1 writes identical values every replay.

#define N_SRC_MAX 25088            // 98 blocks * 256 threads >= 25000

__device__ int g_tgt[N_SRC_MAX];   // composed output row per source row

__global__ void __launch_bounds__(256) zero_chase_kernel(
        float4* __restrict__ out, long long n4,
        const int* __restrict__ idx0,
        const int* __restrict__ idx1,
        const int* __restrict__ idx2,
        int n_rows) {
    int bt = blockIdx.x * 256 + threadIdx.x;

    // Chase (first 98 blocks only): result unused until the end -> overlapped
    // with this thread's zero stores.
    int m = -1;
    bool do_chase = (bt < n_rows);
    if (do_chase) {
        int j = __ldg(&idx2[bt]);
        int k = __ldg(&idx1[j]);
        m = __ldg(&idx0[k]);
    }

    // Pure zero-store stream (the 6.9TB/s pattern — keep byte-identical)
    long long i = (long long)bt;
    long long stride = (long long)gridDim.x * 256;
    const float4 z = make_float4(0.f, 0.f, 0.f, 0.f);
    for (; i < n4; i += stride) {
        out[i] = z;
    }

    if (do_chase) {
        g_tgt[bt] = m;             // coalesced 100KB write
    }
}

// K2: chase-free scatter, 4 chunks per thread from different rows (MLP=4).
// Chunk c (c in [0, n_rows*16)) copies float4 #(c&15) of row (c>>4).
__global__ void __launch_bounds__(256) scatter_kernel(
        const float4* __restrict__ x,
        float4* __restrict__ out,
        int n_chunks, int chunk_stride) {
    int t = blockIdx.x * 256 + threadIdx.x;

    int c[4];
    int tgt[4];
    float4 val[4];
    bool ok[4];

#pragma unroll
    for (int u = 0; u < 4; u++) {
        c[u] = t + u * chunk_stride;
        ok[u] = (c[u] < n_chunks);
    }
    // batch 1: 4 independent target-row loads (L1/L2 broadcast across 16 lanes)
#pragma unroll
    for (int u = 0; u < 4; u++) {
        tgt[u] = ok[u] ? __ldg(&g_tgt[c[u] >> 4]) : 0;
    }
    // batch 2: 4 independent coalesced x loads
#pragma unroll
    for (int u = 0; u < 4; u++) {
        val[u] = ok[u] ? __ldg(&x[(long long)(c[u] >> 4) * 16 + (c[u] & 15)])
                       : make_float4(0.f, 0.f, 0.f, 0.f);
    }
    // batch 3: 4 independent random row-chunk stores
#pragma unroll
    for (int u = 0; u < 4; u++) {
        if (ok[u]) {
            out[(long long)tgt[u] * 16 + (c[u] & 15)] = val[u];
        }
    }
}

extern "C" void kernel_launch(void* const* d_in, const int* in_sizes, int n_in,
                              void* d_out, int out_size) {
    const float* x   = (const float*)d_in[0];
    const int* idx0  = (const int*)d_in[1];
    const int* idx1  = (const int*)d_in[2];
    const int* idx2  = (const int*)d_in[3];
    float* out       = (float*)d_out;

    const int F = 64;
    int n_rows = in_sizes[0] / F;            // 25000
    long long n4 = (long long)out_size / 4;  // 25.6M float4

    // K1: pure-write zero sweep + embedded index chase
    {
        int blocks = 148 * 32;               // 4736
        zero_chase_kernel<<<blocks, 256>>>((float4*)out, n4,
                                           idx0, idx1, idx2, n_rows);
    }

    // K2: scatter 400000 chunks, 4 per thread
    {
        int n_chunks = n_rows * 16;                       // 400000
        int n_threads = (n_chunks + 3) / 4;               // 100000
        int blocks = (n_threads + 255) / 256;             // 391
        int chunk_stride = blocks * 256;                  // 100096
        scatter_kernel<<<blocks, 256>>>((const float4*)x, (float4*)out,
                                        n_chunks, chunk_stride);
    }
}